// round 12
// baseline (speedup 1.0000x reference)
#include <cuda_runtime.h>
#include <cstdint>

// ---------------- problem constants ----------------
#define HEADS_N 4
#define BSZ 2
#define NTOT 8192        // THW
#define MTOT 1024        // HW
#define CVTOT 512
#define M_T 64           // m-tile per block
#define NSPLIT 4
#define NPS (NTOT / NSPLIT)     // 2048
#define NCH 128                 // n per chunk
#define NCHUNKS (NPS / NCH)     // 16
#define NTHREADS 512
#define PSTR 136                // P row stride (== 8 mod 32 -> conflict-free LDS.64)

// ---------------- device scratch (no cudaMalloc allowed) ----------------
__device__ __align__(16) float g_partial[NSPLIT * BSZ * CVTOT * MTOT]; // 16 MB
// Kt fragment-native: [b][h][ngrp(n/16)][ks(4)][lane(32)][4]  (8 MB)
__device__ __align__(16) float g_ktf[BSZ * HEADS_N * (NTOT / 16) * 4 * 128];
__device__ __align__(16) float g_Q [BSZ * HEADS_N * MTOT * 32];        // [b][h][m][32k pairperm] 1 MB
__device__ __align__(16) float g_bias[BSZ * HEADS_N * MTOT];           // 32 KB
// mv fragment-native: [b][cvblk(16)][ngrp(n/8)][half(2)][lane(32)][4]  (33.5 MB)
__device__ __align__(16) float g_mvp[BSZ * CVTOT * NTOT];

// ---------------- smem layout (float offsets) ----------------
#define F_BIAS 0
#define F_MS   256                       // ms[2048] for the whole split
#define F_Q    (F_MS + 2048)             // 2304 : Q[4][64][48]
#define F_P    (F_Q + 4 * 64 * 48)       // 14592 : P[4][64][PSTR]
#define SM_TOTAL ((F_P + 4 * 64 * PSTR) * 4)   // 197632 B

// ---------------- helpers ----------------
__device__ __forceinline__ float rn_tf32(float x) {
    uint32_t u;
    asm("cvt.rna.tf32.f32 %0, %1;" : "=r"(u) : "f"(x));
    return __uint_as_float(u);
}
__device__ __forceinline__ float ex2f(float x) {
    float y;
    asm("ex2.approx.f32 %0, %1;" : "=f"(y) : "f"(x));
    return y;
}
__device__ __forceinline__ void mma_tf32(float* d, float2 aa, float2 ab, float2 bb) {
    asm volatile(
        "mma.sync.aligned.m16n8k8.row.col.f32.tf32.tf32.f32 "
        "{%0,%1,%2,%3},{%4,%5,%6,%7},{%8,%9},{%0,%1,%2,%3};"
        : "+f"(d[0]), "+f"(d[1]), "+f"(d[2]), "+f"(d[3])
        : "r"(__float_as_uint(aa.x)), "r"(__float_as_uint(ab.x)),
          "r"(__float_as_uint(aa.y)), "r"(__float_as_uint(ab.y)),
          "r"(__float_as_uint(bb.x)), "r"(__float_as_uint(bb.y)));
}

// ---------------- precompute kernels ----------------
// Kt fragment-native: value for logical (n, K): K<16 -> mk^3, K>=16 -> mk
__global__ void prep_ktf(const float* __restrict__ mk) {
    int i = blockIdx.x * blockDim.x + threadIdx.x;      // over BSZ*64*NTOT
    if (i >= BSZ * 64 * NTOT) return;
    int n  = i & (NTOT - 1);
    int ck = (i >> 13) & 63;
    int b  = i >> 19;
    float v = mk[i];
    int h = ck >> 4, c = ck & 15;
    int gid = n & 7, half = (n >> 3) & 1, ngrp = n >> 4;
    size_t blk = (((size_t)(b * HEADS_N + h) * (NTOT / 16) + ngrp)) * 4;
    #pragma unroll
    for (int t = 0; t < 2; t++) {
        int K = t ? (16 + c) : c;
        float val = t ? v : (v * v * v);
        int ks = K >> 3, r = K & 7;
        int s = ((r & 3) << 1) | (r >> 2);
        size_t off = (blk + ks) * 128 + ((gid * 4 + (s >> 1)) << 2) + half * 2 + (s & 1);
        g_ktf[off] = rn_tf32(val);
    }
}

// Q pair-ks permuted position of logical k
__device__ __host__ __forceinline__ int qpos(int K) {
    int ks = K >> 3, r = K & 7;
    int s = ((r & 3) << 1) | (r >> 2);
    return (ks >> 1) * 16 + (s >> 1) * 4 + (ks & 1) * 2 + (s & 1);
}

__global__ void prep_q(const float* __restrict__ qk, const float* __restrict__ qe) {
    int i = blockIdx.x * blockDim.x + threadIdx.x;      // over BSZ*4*MTOT
    if (i >= BSZ * HEADS_N * MTOT) return;
    int m = i & (MTOT - 1);
    int h = (i >> 10) & 3;
    int b = i >> 12;
    size_t qb = (size_t)i * 32;
    float bias = 0.0f;
    #pragma unroll
    for (int c = 0; c < 16; c++) {
        size_t gi = ((size_t)(b * 64 + h * 16 + c)) * MTOT + m;
        float e = qe[gi];
        float k = qk[gi];
        g_Q[qb + qpos(c)]      = rn_tf32(-e);
        g_Q[qb + qpos(16 + c)] = rn_tf32(2.0f * k * e);
        bias += e * k * k * k;
    }
    g_bias[i] = bias;
}

// gather-style: one thread -> one output float4 (coalesced STG.128)
__global__ void prep_mv(const float* __restrict__ mv) {
    int f = blockIdx.x * blockDim.x + threadIdx.x;   // float4 index
    if (f >= BSZ * CVTOT * NTOT / 4) return;
    int tig  = f & 3;
    int gid  = (f >> 2) & 7;
    int half = (f >> 5) & 1;
    int ngrp = (f >> 6) & (NTOT / 8 - 1);
    int blk  = (f >> 16) & 15;
    int b    = f >> 20;
    int n0  = ngrp * 8 + tig;
    int cvb = blk * 32 + half * 16 + gid;
    const float* src = mv + ((size_t)(b * CVTOT) << 13);
    float4 v;
    v.x = rn_tf32(src[((size_t)cvb << 13) + n0]);
    v.y = rn_tf32(src[((size_t)cvb << 13) + n0 + 4]);
    v.z = rn_tf32(src[((size_t)(cvb + 8) << 13) + n0]);
    v.w = rn_tf32(src[((size_t)(cvb + 8) << 13) + n0 + 4]);
    *(float4*)(g_mvp + ((size_t)f << 2)) = v;
}

// ---------------- main fused kernel ----------------
__global__ void __launch_bounds__(NTHREADS, 1)
mr_main(const float* __restrict__ ms)
{
    extern __shared__ float sm[];
    const int tid  = threadIdx.x;
    const int w    = tid >> 5;
    const int lane = tid & 31;
    const int gid  = lane >> 2;      // 0..7
    const int tig  = lane & 3;       // 0..3

    const int bx    = blockIdx.x;    // 128 blocks
    const int split = bx & 3;
    const int mtile = (bx >> 2) & 15;
    const int b     = bx >> 6;
    const int m0    = mtile * M_T;
    const int nbase = split * NPS;

    // ---- stage bias + ms (whole split) + Q (block-constant) ----
    if (tid < 256)
        sm[F_BIAS + tid] = g_bias[(size_t)(b * HEADS_N + (tid >> 6)) * MTOT + m0 + (tid & 63)];
    #pragma unroll
    for (int it = 0; it < 4; it++) {
        int i = tid + it * NTHREADS;
        sm[F_MS + i] = ms[(size_t)b * NTOT + nbase + i];
    }
    {
        const float4* src = (const float4*)(g_Q + (size_t)(b * HEADS_N) * MTOT * 32);
        #pragma unroll
        for (int it = 0; it < 4; it++) {
            int j = tid + it * NTHREADS;         // 2048 float4
            int kq = j & 7, mm = (j >> 3) & 63, h = j >> 9;
            float4 v = src[((size_t)h * MTOT + m0 + mm) * 8 + kq];
            *(float4*)(sm + F_Q + (h * 64 + mm) * 48 + kq * 4) = v;
        }
    }

    // Phase A mapping: warp = (ntile, mtile4), all 4 heads in-register
    const int nt  = w & 3;
    const int mA0 = (w >> 2) * 16;
    // Phase B mapping: one head per warp, cv32 x m64
    const int headB = w >> 2;
    const int cvg   = w & 3;

    float acc[2][8][4];   // O accumulators [cvtile][mt][reg]
    #pragma unroll
    for (int rt = 0; rt < 2; rt++)
        #pragma unroll
        for (int mt = 0; mt < 8; mt++)
            #pragma unroll
            for (int r = 0; r < 4; r++) acc[rt][mt][r] = 0.0f;

    // fragment-native bases
    const float* gvf = g_mvp +
        (((size_t)(b * 16 + headB * 4 + cvg)) * (NTOT / 8)) * 256;
    const float* ktb0 = g_ktf + ((size_t)(b * HEADS_N) * (NTOT / 16)) * 512;
    const float* pb = sm + F_P + headB * (64 * PSTR);

    const float SC = 0.18033688f;   // 0.125 * log2(e)

    __syncthreads();

    for (int chunk = 0; chunk < NCHUNKS; chunk++) {
        const int n0 = nbase + chunk * NCH;

        // ---- prefetch Phase-B ks=0 mv fragments (hidden under Phase A) ----
        float4 fv0, fv1;
        {
            const float* nb = gvf + (((size_t)(n0 >> 3)) << 8);
            fv0 = *(const float4*)(nb + lane * 4);
            fv1 = *(const float4*)(nb + 128 + lane * 4);
        }

        // ===== Phase A: two 64-n sub-passes =====
        #pragma unroll
        for (int p = 0; p < 2; p++) {
            float sacc[4][2][4];
            #pragma unroll
            for (int h = 0; h < 4; h++)
                #pragma unroll
                for (int j = 0; j < 2; j++)
                    #pragma unroll
                    for (int r = 0; r < 4; r++) sacc[h][j][r] = 0.0f;

            const int ngrp = (n0 >> 4) + p * 4 + nt;
            const float* kbase = ktb0 + (size_t)ngrp * 512 + lane * 4;

            // software-pipelined over 8 steps: it = kp*4 + h
            float4 fA0, fA1;
            {
                const float* kb = kbase;   // h=0, kp=0
                fA0 = *(const float4*)(kb);
                fA1 = *(const float4*)(kb + 128);
            }
            #pragma unroll
            for (int it = 0; it < 8; it++) {
                const int kp = it >> 2, h = it & 3;
                float4 nA0, nA1;
                if (it < 7) {
                    const int it2 = it + 1;
                    const int kp2 = it2 >> 2, h2 = it2 & 3;
                    const float* kb = kbase +
                        ((size_t)h2 * (NTOT / 16) * 4 + 2 * kp2) * 128;
                    nA0 = *(const float4*)(kb);
                    nA1 = *(const float4*)(kb + 128);
                }
                const float* qb = sm + F_Q + h * 3072 + kp * 16 + tig * 4;
                #pragma unroll
                for (int j = 0; j < 2; j++) {
                    float4 bq = *(const float4*)(qb + (mA0 + j * 8 + gid) * 48);
                    mma_tf32(sacc[h][j], make_float2(fA0.x, fA0.y),
                             make_float2(fA0.z, fA0.w), make_float2(bq.x, bq.y));
                    mma_tf32(sacc[h][j], make_float2(fA1.x, fA1.y),
                             make_float2(fA1.z, fA1.w), make_float2(bq.z, bq.w));
                }
                fA0 = nA0; fA1 = nA1;
            }

            // ---- softmax over heads, in registers (log2 domain, no max) ----
            {
                const int nAl = p * 64 + nt * 16 + gid;
                const float msa = sm[F_MS + chunk * NCH + nAl] * SC;
                const float msb = sm[F_MS + chunk * NCH + nAl + 8] * SC;
                #pragma unroll
                for (int j = 0; j < 2; j++) {
                    #pragma unroll
                    for (int c = 0; c < 2; c++) {
                        int m = mA0 + j * 8 + 2 * tig + c;
                        float b0 = sm[F_BIAS + m];
                        float b1 = sm[F_BIAS + 64 + m];
                        float b2 = sm[F_BIAS + 128 + m];
                        float b3 = sm[F_BIAS + 192 + m];
                        {
                            float e0 = ex2f((sacc[0][j][c] - b0) * msa);
                            float e1 = ex2f((sacc[1][j][c] - b1) * msa);
                            float e2 = ex2f((sacc[2][j][c] - b2) * msa);
                            float e3 = ex2f((sacc[3][j][c] - b3) * msa);
                            float inv = __fdividef(1.0f, e0 + e1 + e2 + e3 + 1e-30f);
                            sacc[0][j][c] = rn_tf32(e0 * inv);
                            sacc[1][j][c] = rn_tf32(e1 * inv);
                            sacc[2][j][c] = rn_tf32(e2 * inv);
                            sacc[3][j][c] = rn_tf32(e3 * inv);
                        }
                        {
                            float e0 = ex2f((sacc[0][j][2 + c] - b0) * msb);
                            float e1 = ex2f((sacc[1][j][2 + c] - b1) * msb);
                            float e2 = ex2f((sacc[2][j][2 + c] - b2) * msb);
                            float e3 = ex2f((sacc[3][j][2 + c] - b3) * msb);
                            float inv = __fdividef(1.0f, e0 + e1 + e2 + e3 + 1e-30f);
                            sacc[0][j][2 + c] = rn_tf32(e0 * inv);
                            sacc[1][j][2 + c] = rn_tf32(e1 * inv);
                            sacc[2][j][2 + c] = rn_tf32(e2 * inv);
                            sacc[3][j][2 + c] = rn_tf32(e3 * inv);
                        }
                    }
                }
            }

            // ---- scatter-store P[h][m][npos] ----
            {
                const int pos0 = p * 64 + nt * 16 + ((gid & 3) << 1) + (gid >> 2);
                #pragma unroll
                for (int h = 0; h < 4; h++) {
                    #pragma unroll
                    for (int j = 0; j < 2; j++) {
                        float* sp = sm + F_P + h * (64 * PSTR) + (mA0 + j * 8 + 2 * tig) * PSTR;
                        sp[pos0]            = sacc[h][j][0];
                        sp[PSTR + pos0]     = sacc[h][j][1];
                        sp[pos0 + 8]        = sacc[h][j][2];
                        sp[PSTR + pos0 + 8] = sacc[h][j][3];
                    }
                }
            }
        }
        __syncthreads();

        // ===== Phase B: O += mv * P over 128 n (1-step load lookahead) =====
        #pragma unroll
        for (int ks = 0; ks < 16; ks++) {
            float4 g0, g1;
            if (ks < 15) {
                const float* nb = gvf + (((size_t)(n0 >> 3) + ks + 1) << 8);
                g0 = *(const float4*)(nb + lane * 4);
                g1 = *(const float4*)(nb + 128 + lane * 4);
            }
            float2 a0 = { fv0.x, fv0.y }, a1 = { fv0.z, fv0.w };
            float2 a2 = { fv1.x, fv1.y }, a3 = { fv1.z, fv1.w };
            #pragma unroll
            for (int mt = 0; mt < 8; mt++) {
                float2 bb = *(const float2*)(pb + (mt * 8 + gid) * PSTR + ks * 8 + 2 * tig);
                mma_tf32(acc[0][mt], a0, a1, bb);
                mma_tf32(acc[1][mt], a2, a3, bb);
            }
            fv0 = g0; fv1 = g1;
        }
        __syncthreads();
    }

    // ---- writeout: fragment-direct STG.64 into g_partial ----
    {
        float* pp = g_partial +
            ((size_t)(split * BSZ + b) * CVTOT + headB * 128 + cvg * 32) * MTOT + m0;
        #pragma unroll
        for (int rt = 0; rt < 2; rt++) {
            #pragma unroll
            for (int mt = 0; mt < 8; mt++) {
                int r0 = rt * 16 + gid;
                int m  = mt * 8 + 2 * tig;
                float2 lo = { acc[rt][mt][0], acc[rt][mt][1] };
                float2 hi = { acc[rt][mt][2], acc[rt][mt][3] };
                *(float2*)(pp + (size_t)r0 * MTOT + m)       = lo;
                *(float2*)(pp + (size_t)(r0 + 8) * MTOT + m) = hi;
            }
        }
    }
}

// ---------------- assemble: reduce splits + copy qv ----------------
__global__ void assemble_kernel(const float* __restrict__ qv, float* __restrict__ out)
{
    const int total4 = BSZ * 2 * CVTOT * MTOT / 4;
    int idx = blockIdx.x * blockDim.x + threadIdx.x;
    if (idx >= total4) return;
    int gf  = idx * 4;
    int b   = gf >> 20;
    int rem = gf & ((1 << 20) - 1);
    int ch  = rem >> 10;
    int m   = rem & 1023;

    float4 r;
    if (ch < CVTOT) {
        const size_t stride = (size_t)BSZ * CVTOT * MTOT;
        size_t off = ((size_t)b * CVTOT + ch) * MTOT + m;
        float4 a0 = *reinterpret_cast<const float4*>(g_partial + 0 * stride + off);
        float4 a1 = *reinterpret_cast<const float4*>(g_partial + 1 * stride + off);
        float4 a2 = *reinterpret_cast<const float4*>(g_partial + 2 * stride + off);
        float4 a3 = *reinterpret_cast<const float4*>(g_partial + 3 * stride + off);
        r.x = a0.x + a1.x + a2.x + a3.x;
        r.y = a0.y + a1.y + a2.y + a3.y;
        r.z = a0.z + a1.z + a2.z + a3.z;
        r.w = a0.w + a1.w + a2.w + a3.w;
    } else {
        r = *reinterpret_cast<const float4*>(
                qv + ((size_t)b * CVTOT + (ch - CVTOT)) * MTOT + m);
    }
    *reinterpret_cast<float4*>(out + (size_t)gf) = r;
}

extern "C" void kernel_launch(void* const* d_in, const int* in_sizes, int n_in,
                              void* d_out, int out_size)
{
    const float* mk = (const float*)d_in[0];
    const float* qk = (const float*)d_in[1];
    const float* ms = (const float*)d_in[2];
    const float* qe = (const float*)d_in[3];
    const float* mv = (const float*)d_in[4];
    const float* qv = (const float*)d_in[5];
    float* out = (float*)d_out;

    prep_ktf<<<(BSZ * 64 * NTOT + 255) / 256, 256>>>(mk);
    prep_q<<<(BSZ * HEADS_N * MTOT + 255) / 256, 256>>>(qk, qe);
    prep_mv<<<(BSZ * CVTOT * NTOT / 4 + 255) / 256, 256>>>(mv);

    cudaFuncSetAttribute(mr_main, cudaFuncAttributeMaxDynamicSharedMemorySize,
                         SM_TOTAL);
    mr_main<<<BSZ * 16 * NSPLIT, NTHREADS, SM_TOTAL>>>(ms);

    const int total4 = BSZ * 2 * CVTOT * MTOT / 4;
    assemble_kernel<<<(total4 + 255) / 256, 256>>>(qv, out);
}

// round 13
// speedup vs baseline: 1.0958x; 1.0958x over previous
#include <cuda_runtime.h>
#include <cstdint>

// ---------------- problem constants ----------------
#define HEADS_N 4
#define BSZ 2
#define NTOT 8192        // THW
#define MTOT 1024        // HW
#define CVTOT 512
#define M_T 32           // m-tile per block
#define NSPLIT 8
#define NPS (NTOT / NSPLIT)     // 1024
#define NCH 128                 // n per chunk
#define NCHUNKS (NPS / NCH)     // 8
#define NTHREADS 256
#define PSTR 136                // P row stride (== 8 mod 32 -> conflict-free LDS.64)

// ---------------- device scratch (no cudaMalloc allowed) ----------------
__device__ __align__(16) float g_partial[NSPLIT * BSZ * CVTOT * MTOT]; // 32 MB
// Kt fragment-native: [b][h][ngrp(n/16)][ks(4)][lane(32)][4]  (8 MB)
__device__ __align__(16) float g_ktf[BSZ * HEADS_N * (NTOT / 16) * 4 * 128];
__device__ __align__(16) float g_Q [BSZ * HEADS_N * MTOT * 32];        // [b][h][m][32k pairperm] 1 MB
__device__ __align__(16) float g_bias[BSZ * HEADS_N * MTOT];           // 32 KB
// mv fragment-native: [b][cvblk(16)][ngrp(n/8)][half(2)][lane(32)][4]  (33.5 MB)
__device__ __align__(16) float g_mvp[BSZ * CVTOT * NTOT];

// ---------------- smem layout (float offsets) ----------------
#define F_BIAS 0                          // bias[4][32]
#define F_MS   128                        // ms[1024] for the whole split
#define F_Q    (F_MS + NPS)               // 1152 : Q[4][32][48]
#define F_P    (F_Q + 4 * 32 * 48)        // 7296 : P[4][32][PSTR]
#define SM_TOTAL ((F_P + 4 * 32 * PSTR) * 4)   // 98816 B

// ---------------- helpers ----------------
__device__ __forceinline__ float rn_tf32(float x) {
    uint32_t u;
    asm("cvt.rna.tf32.f32 %0, %1;" : "=r"(u) : "f"(x));
    return __uint_as_float(u);
}
__device__ __forceinline__ float ex2f(float x) {
    float y;
    asm("ex2.approx.f32 %0, %1;" : "=f"(y) : "f"(x));
    return y;
}
__device__ __forceinline__ void mma_tf32(float* d, float2 aa, float2 ab, float2 bb) {
    asm volatile(
        "mma.sync.aligned.m16n8k8.row.col.f32.tf32.tf32.f32 "
        "{%0,%1,%2,%3},{%4,%5,%6,%7},{%8,%9},{%0,%1,%2,%3};"
        : "+f"(d[0]), "+f"(d[1]), "+f"(d[2]), "+f"(d[3])
        : "r"(__float_as_uint(aa.x)), "r"(__float_as_uint(ab.x)),
          "r"(__float_as_uint(aa.y)), "r"(__float_as_uint(ab.y)),
          "r"(__float_as_uint(bb.x)), "r"(__float_as_uint(bb.y)));
}

// ---------------- precompute kernels ----------------
__global__ void prep_ktf(const float* __restrict__ mk) {
    int i = blockIdx.x * blockDim.x + threadIdx.x;      // over BSZ*64*NTOT
    if (i >= BSZ * 64 * NTOT) return;
    int n  = i & (NTOT - 1);
    int ck = (i >> 13) & 63;
    int b  = i >> 19;
    float v = mk[i];
    int h = ck >> 4, c = ck & 15;
    int gid = n & 7, half = (n >> 3) & 1, ngrp = n >> 4;
    size_t blk = (((size_t)(b * HEADS_N + h) * (NTOT / 16) + ngrp)) * 4;
    #pragma unroll
    for (int t = 0; t < 2; t++) {
        int K = t ? (16 + c) : c;
        float val = t ? v : (v * v * v);
        int ks = K >> 3, r = K & 7;
        int s = ((r & 3) << 1) | (r >> 2);
        size_t off = (blk + ks) * 128 + ((gid * 4 + (s >> 1)) << 2) + half * 2 + (s & 1);
        g_ktf[off] = rn_tf32(val);
    }
}

__device__ __host__ __forceinline__ int qpos(int K) {
    int ks = K >> 3, r = K & 7;
    int s = ((r & 3) << 1) | (r >> 2);
    return (ks >> 1) * 16 + (s >> 1) * 4 + (ks & 1) * 2 + (s & 1);
}

__global__ void prep_q(const float* __restrict__ qk, const float* __restrict__ qe) {
    int i = blockIdx.x * blockDim.x + threadIdx.x;      // over BSZ*4*MTOT
    if (i >= BSZ * HEADS_N * MTOT) return;
    int m = i & (MTOT - 1);
    int h = (i >> 10) & 3;
    int b = i >> 12;
    size_t qb = (size_t)i * 32;
    float bias = 0.0f;
    #pragma unroll
    for (int c = 0; c < 16; c++) {
        size_t gi = ((size_t)(b * 64 + h * 16 + c)) * MTOT + m;
        float e = qe[gi];
        float k = qk[gi];
        g_Q[qb + qpos(c)]      = rn_tf32(-e);
        g_Q[qb + qpos(16 + c)] = rn_tf32(2.0f * k * e);
        bias += e * k * k * k;
    }
    g_bias[i] = bias;
}

// gather-style: one thread -> one output float4 (coalesced STG.128)
__global__ void prep_mv(const float* __restrict__ mv) {
    int f = blockIdx.x * blockDim.x + threadIdx.x;   // float4 index
    if (f >= BSZ * CVTOT * NTOT / 4) return;
    int tig  = f & 3;
    int gid  = (f >> 2) & 7;
    int half = (f >> 5) & 1;
    int ngrp = (f >> 6) & (NTOT / 8 - 1);
    int blk  = (f >> 16) & 15;
    int b    = f >> 20;
    int n0  = ngrp * 8 + tig;
    int cvb = blk * 32 + half * 16 + gid;
    const float* src = mv + ((size_t)(b * CVTOT) << 13);
    float4 v;
    v.x = rn_tf32(src[((size_t)cvb << 13) + n0]);
    v.y = rn_tf32(src[((size_t)cvb << 13) + n0 + 4]);
    v.z = rn_tf32(src[((size_t)(cvb + 8) << 13) + n0]);
    v.w = rn_tf32(src[((size_t)(cvb + 8) << 13) + n0 + 4]);
    *(float4*)(g_mvp + ((size_t)f << 2)) = v;
}

// ---------------- main fused kernel ----------------
__global__ void __launch_bounds__(NTHREADS, 2)
mr_main(const float* __restrict__ ms)
{
    extern __shared__ float sm[];
    const int tid  = threadIdx.x;
    const int w    = tid >> 5;       // 0..7
    const int lane = tid & 31;
    const int gid  = lane >> 2;      // 0..7
    const int tig  = lane & 3;       // 0..3

    const int bx    = blockIdx.x;    // 512 blocks
    const int split = bx & 7;
    const int mtile = (bx >> 3) & 31;
    const int b     = bx >> 8;
    const int m0    = mtile * M_T;
    const int nbase = split * NPS;

    // ---- stage bias + ms (whole split) + Q (block-constant) ----
    if (tid < 128)
        sm[F_BIAS + tid] = g_bias[(size_t)(b * HEADS_N + (tid >> 5)) * MTOT + m0 + (tid & 31)];
    #pragma unroll
    for (int it = 0; it < NPS / NTHREADS; it++) {
        int i = tid + it * NTHREADS;
        sm[F_MS + i] = ms[(size_t)b * NTOT + nbase + i];
    }
    {
        const float4* src = (const float4*)(g_Q + (size_t)(b * HEADS_N) * MTOT * 32);
        #pragma unroll
        for (int it = 0; it < 4; it++) {
            int j = tid + it * NTHREADS;         // 1024 float4
            int kq = j & 7, mm = (j >> 3) & 31, h = j >> 8;
            float4 v = src[((size_t)h * MTOT + m0 + mm) * 8 + kq];
            *(float4*)(sm + F_Q + (h * 32 + mm) * 48 + kq * 4) = v;
        }
    }

    // Phase A mapping: warp = (ntile 0..3, mtile2 0..1), all 4 heads in-register
    const int nt  = w & 3;
    const int mA0 = (w >> 2) * 16;
    // Phase B mapping: one head per 2 warps, 64cv x 32m per warp
    const int headB = w >> 1;
    const int cvq   = w & 1;

    float acc[4][4][4];   // O accumulators [cvfrag(2blk x 2half)][mt][reg]
    #pragma unroll
    for (int rt = 0; rt < 4; rt++)
        #pragma unroll
        for (int mt = 0; mt < 4; mt++)
            #pragma unroll
            for (int r = 0; r < 4; r++) acc[rt][mt][r] = 0.0f;

    // fragment-native bases (two 32-cv blocks per warp)
    const size_t blkbase = (size_t)(b * 16 + headB * 4 + cvq * 2);
    const float* gvf0 = g_mvp + blkbase * (NTOT / 8) * 256;
    const float* gvf1 = gvf0 + (size_t)(NTOT / 8) * 256;
    const float* ktb0 = g_ktf + ((size_t)(b * HEADS_N) * (NTOT / 16)) * 512;
    const float* pb = sm + F_P + headB * (32 * PSTR);

    const float SC = 0.18033688f;   // 0.125 * log2(e)

    __syncthreads();

    for (int chunk = 0; chunk < NCHUNKS; chunk++) {
        const int n0 = nbase + chunk * NCH;

        // ===== Phase A: two 64-n sub-passes =====
        #pragma unroll
        for (int p = 0; p < 2; p++) {
            float sacc[4][2][4];
            #pragma unroll
            for (int h = 0; h < 4; h++)
                #pragma unroll
                for (int j = 0; j < 2; j++)
                    #pragma unroll
                    for (int r = 0; r < 4; r++) sacc[h][j][r] = 0.0f;

            const int ngrp = (n0 >> 4) + p * 4 + nt;
            #pragma unroll
            for (int kp = 0; kp < 2; kp++) {
                #pragma unroll
                for (int h = 0; h < 4; h++) {
                    const float* kb = ktb0 +
                        (((size_t)h * (NTOT / 16) + ngrp) * 4 + 2 * kp) * 128 + lane * 4;
                    float4 fA0 = *(const float4*)(kb);
                    float4 fA1 = *(const float4*)(kb + 128);
                    const float* qb = sm + F_Q + h * 1536 + kp * 16 + tig * 4;
                    #pragma unroll
                    for (int j = 0; j < 2; j++) {
                        float4 bq = *(const float4*)(qb + (mA0 + j * 8 + gid) * 48);
                        mma_tf32(sacc[h][j], make_float2(fA0.x, fA0.y),
                                 make_float2(fA0.z, fA0.w), make_float2(bq.x, bq.y));
                        mma_tf32(sacc[h][j], make_float2(fA1.x, fA1.y),
                                 make_float2(fA1.z, fA1.w), make_float2(bq.z, bq.w));
                    }
                }
            }

            // ---- softmax over heads, in registers (log2 domain, no max) ----
            {
                const int nAl = p * 64 + nt * 16 + gid;
                const float msa = sm[F_MS + chunk * NCH + nAl] * SC;
                const float msb = sm[F_MS + chunk * NCH + nAl + 8] * SC;
                #pragma unroll
                for (int j = 0; j < 2; j++) {
                    #pragma unroll
                    for (int c = 0; c < 2; c++) {
                        int m = mA0 + j * 8 + 2 * tig + c;
                        float b0 = sm[F_BIAS + m];
                        float b1 = sm[F_BIAS + 32 + m];
                        float b2 = sm[F_BIAS + 64 + m];
                        float b3 = sm[F_BIAS + 96 + m];
                        {
                            float e0 = ex2f((sacc[0][j][c] - b0) * msa);
                            float e1 = ex2f((sacc[1][j][c] - b1) * msa);
                            float e2 = ex2f((sacc[2][j][c] - b2) * msa);
                            float e3 = ex2f((sacc[3][j][c] - b3) * msa);
                            float inv = __fdividef(1.0f, e0 + e1 + e2 + e3 + 1e-30f);
                            sacc[0][j][c] = rn_tf32(e0 * inv);
                            sacc[1][j][c] = rn_tf32(e1 * inv);
                            sacc[2][j][c] = rn_tf32(e2 * inv);
                            sacc[3][j][c] = rn_tf32(e3 * inv);
                        }
                        {
                            float e0 = ex2f((sacc[0][j][2 + c] - b0) * msb);
                            float e1 = ex2f((sacc[1][j][2 + c] - b1) * msb);
                            float e2 = ex2f((sacc[2][j][2 + c] - b2) * msb);
                            float e3 = ex2f((sacc[3][j][2 + c] - b3) * msb);
                            float inv = __fdividef(1.0f, e0 + e1 + e2 + e3 + 1e-30f);
                            sacc[0][j][2 + c] = rn_tf32(e0 * inv);
                            sacc[1][j][2 + c] = rn_tf32(e1 * inv);
                            sacc[2][j][2 + c] = rn_tf32(e2 * inv);
                            sacc[3][j][2 + c] = rn_tf32(e3 * inv);
                        }
                    }
                }
            }

            // ---- scatter-store P[h][m][npos] ----
            {
                const int pos0 = p * 64 + nt * 16 + ((gid & 3) << 1) + (gid >> 2);
                #pragma unroll
                for (int h = 0; h < 4; h++) {
                    #pragma unroll
                    for (int j = 0; j < 2; j++) {
                        float* sp = sm + F_P + h * (32 * PSTR) + (mA0 + j * 8 + 2 * tig) * PSTR;
                        sp[pos0]            = sacc[h][j][0];
                        sp[PSTR + pos0]     = sacc[h][j][1];
                        sp[pos0 + 8]        = sacc[h][j][2];
                        sp[PSTR + pos0 + 8] = sacc[h][j][3];
                    }
                }
            }
        }
        __syncthreads();

        // ===== Phase B: O += mv * P over 128 n =====
        #pragma unroll
        for (int ks = 0; ks < 16; ks++) {
            const size_t nidx = ((size_t)(n0 >> 3) + ks) << 8;
            float4 f0 = *(const float4*)(gvf0 + nidx + lane * 4);
            float4 f1 = *(const float4*)(gvf0 + nidx + 128 + lane * 4);
            float4 f2 = *(const float4*)(gvf1 + nidx + lane * 4);
            float4 f3 = *(const float4*)(gvf1 + nidx + 128 + lane * 4);
            float2 a0 = { f0.x, f0.y }, a1 = { f0.z, f0.w };
            float2 a2 = { f1.x, f1.y }, a3 = { f1.z, f1.w };
            float2 a4 = { f2.x, f2.y }, a5 = { f2.z, f2.w };
            float2 a6 = { f3.x, f3.y }, a7 = { f3.z, f3.w };
            #pragma unroll
            for (int mt = 0; mt < 4; mt++) {
                float2 bb = *(const float2*)(pb + (mt * 8 + gid) * PSTR + ks * 8 + 2 * tig);
                mma_tf32(acc[0][mt], a0, a1, bb);
                mma_tf32(acc[1][mt], a2, a3, bb);
                mma_tf32(acc[2][mt], a4, a5, bb);
                mma_tf32(acc[3][mt], a6, a7, bb);
            }
        }
        __syncthreads();
    }

    // ---- writeout: fragment-direct STG.64 into g_partial ----
    {
        const int cv0 = headB * 128 + cvq * 64;
        float* pp = g_partial +
            ((size_t)(split * BSZ + b) * CVTOT + cv0) * MTOT + m0;
        #pragma unroll
        for (int rt = 0; rt < 4; rt++) {
            int rowbase = (rt >> 1) * 32 + (rt & 1) * 16;
            #pragma unroll
            for (int mt = 0; mt < 4; mt++) {
                int m = mt * 8 + 2 * tig;
                float2 lo = { acc[rt][mt][0], acc[rt][mt][1] };
                float2 hi = { acc[rt][mt][2], acc[rt][mt][3] };
                *(float2*)(pp + (size_t)(rowbase + gid) * MTOT + m)     = lo;
                *(float2*)(pp + (size_t)(rowbase + gid + 8) * MTOT + m) = hi;
            }
        }
    }
}

// ---------------- assemble: reduce 8 splits + copy qv ----------------
__global__ void assemble_kernel(const float* __restrict__ qv, float* __restrict__ out)
{
    const int total4 = BSZ * 2 * CVTOT * MTOT / 4;
    int idx = blockIdx.x * blockDim.x + threadIdx.x;
    if (idx >= total4) return;
    int gf  = idx * 4;
    int b   = gf >> 20;
    int rem = gf & ((1 << 20) - 1);
    int ch  = rem >> 10;
    int m   = rem & 1023;

    float4 r;
    if (ch < CVTOT) {
        const size_t stride = (size_t)BSZ * CVTOT * MTOT;
        size_t off = ((size_t)b * CVTOT + ch) * MTOT + m;
        r = make_float4(0.f, 0.f, 0.f, 0.f);
        #pragma unroll
        for (int s = 0; s < NSPLIT; s++) {
            float4 a = *reinterpret_cast<const float4*>(g_partial + s * stride + off);
            r.x += a.x; r.y += a.y; r.z += a.z; r.w += a.w;
        }
    } else {
        r = *reinterpret_cast<const float4*>(
                qv + ((size_t)b * CVTOT + (ch - CVTOT)) * MTOT + m);
    }
    *reinterpret_cast<float4*>(out + (size_t)gf) = r;
}

extern "C" void kernel_launch(void* const* d_in, const int* in_sizes, int n_in,
                              void* d_out, int out_size)
{
    const float* mk = (const float*)d_in[0];
    const float* qk = (const float*)d_in[1];
    const float* ms = (const float*)d_in[2];
    const float* qe = (const float*)d_in[3];
    const float* mv = (const float*)d_in[4];
    const float* qv = (const float*)d_in[5];
    float* out = (float*)d_out;

    prep_ktf<<<(BSZ * 64 * NTOT + 255) / 256, 256>>>(mk);
    prep_q<<<(BSZ * HEADS_N * MTOT + 255) / 256, 256>>>(qk, qe);
    prep_mv<<<(BSZ * CVTOT * NTOT / 4 + 255) / 256, 256>>>(mv);

    cudaFuncSetAttribute(mr_main, cudaFuncAttributeMaxDynamicSharedMemorySize,
                         SM_TOTAL);
    mr_main<<<BSZ * (MTOT / M_T) * NSPLIT, NTHREADS, SM_TOTAL>>>(ms);

    const int total4 = BSZ * 2 * CVTOT * MTOT / 4;
    assemble_kernel<<<(total4 + 255) / 256, 256>>>(qv, out);
}

// round 14
// speedup vs baseline: 1.6275x; 1.4852x over previous
#include <cuda_runtime.h>
#include <cuda_fp16.h>
#include <cstdint>

// ---------------- problem constants ----------------
#define HEADS_N 4
#define BSZ 2
#define NTOT 8192        // THW
#define MTOT 1024        // HW
#define CVTOT 512
#define M_T 32           // m-tile per block
#define NSPLIT 8
#define NPS (NTOT / NSPLIT)     // 1024
#define NCH 128                 // n per chunk
#define NCHUNKS (NPS / NCH)     // 8
#define NTHREADS 256
#define PSTRH 144               // P row stride in halves (word stride 72 == 8 mod 32)

// ---------------- device scratch (no cudaMalloc allowed) ----------------
__device__ __align__(16) float g_partial[NSPLIT * BSZ * CVTOT * MTOT]; // 32 MB
// Kt fragment-native (tf32): [b][h][ngrp(n/16)][ks(4)][lane(32)][4]  (8 MB)
__device__ __align__(16) float g_ktf[BSZ * HEADS_N * (NTOT / 16) * 4 * 128];
__device__ __align__(16) float g_Q [BSZ * HEADS_N * MTOT * 32];        // [b][h][m][32k pairperm] 1 MB
__device__ __align__(16) float g_bias[BSZ * HEADS_N * MTOT];           // 32 KB
// mv fp16 fragment-native for m16n8k16: [b][B16(32)][ngrp(512)][lane(32)][8 halves] (16.7 MB)
__device__ __align__(16) __half g_mvph[BSZ * CVTOT * NTOT];

// ---------------- smem layout (float offsets) ----------------
#define F_BIAS 0                          // bias[4][32]
#define F_MS   128                        // ms[1024] for the whole split
#define F_Q    (F_MS + NPS)               // 1152 : Q[4][32][48] tf32
#define F_P    (F_Q + 4 * 32 * 48)        // 7296 : P fp16 [4h][32m][PSTRH]
#define SM_TOTAL ((F_P + 4 * 32 * PSTRH / 2) * 4)   // 66048 B

// ---------------- helpers ----------------
__device__ __forceinline__ float rn_tf32(float x) {
    uint32_t u;
    asm("cvt.rna.tf32.f32 %0, %1;" : "=r"(u) : "f"(x));
    return __uint_as_float(u);
}
__device__ __forceinline__ float ex2f(float x) {
    float y;
    asm("ex2.approx.f32 %0, %1;" : "=f"(y) : "f"(x));
    return y;
}
// pack (lo, hi) floats into fp16x2 (lo -> low half)
__device__ __forceinline__ uint32_t pack_h2(float lo, float hi) {
    uint32_t r;
    asm("cvt.rn.f16x2.f32 %0, %1, %2;" : "=r"(r) : "f"(hi), "f"(lo));
    return r;
}
__device__ __forceinline__ void mma_tf32(float* d, float2 aa, float2 ab, float2 bb) {
    asm volatile(
        "mma.sync.aligned.m16n8k8.row.col.f32.tf32.tf32.f32 "
        "{%0,%1,%2,%3},{%4,%5,%6,%7},{%8,%9},{%0,%1,%2,%3};"
        : "+f"(d[0]), "+f"(d[1]), "+f"(d[2]), "+f"(d[3])
        : "r"(__float_as_uint(aa.x)), "r"(__float_as_uint(ab.x)),
          "r"(__float_as_uint(aa.y)), "r"(__float_as_uint(ab.y)),
          "r"(__float_as_uint(bb.x)), "r"(__float_as_uint(bb.y)));
}
__device__ __forceinline__ void mma_f16(float* d, uint4 a, uint2 b) {
    asm volatile(
        "mma.sync.aligned.m16n8k16.row.col.f32.f16.f16.f32 "
        "{%0,%1,%2,%3},{%4,%5,%6,%7},{%8,%9},{%0,%1,%2,%3};"
        : "+f"(d[0]), "+f"(d[1]), "+f"(d[2]), "+f"(d[3])
        : "r"(a.x), "r"(a.y), "r"(a.z), "r"(a.w), "r"(b.x), "r"(b.y));
}

// ---------------- precompute kernels ----------------
__global__ void prep_ktf(const float* __restrict__ mk) {
    int i = blockIdx.x * blockDim.x + threadIdx.x;      // over BSZ*64*NTOT
    if (i >= BSZ * 64 * NTOT) return;
    int n  = i & (NTOT - 1);
    int ck = (i >> 13) & 63;
    int b  = i >> 19;
    float v = mk[i];
    int h = ck >> 4, c = ck & 15;
    int gid = n & 7, half = (n >> 3) & 1, ngrp = n >> 4;
    size_t blk = (((size_t)(b * HEADS_N + h) * (NTOT / 16) + ngrp)) * 4;
    #pragma unroll
    for (int t = 0; t < 2; t++) {
        int K = t ? (16 + c) : c;
        float val = t ? v : (v * v * v);
        int ks = K >> 3, r = K & 7;
        int s = ((r & 3) << 1) | (r >> 2);
        size_t off = (blk + ks) * 128 + ((gid * 4 + (s >> 1)) << 2) + half * 2 + (s & 1);
        g_ktf[off] = rn_tf32(val);
    }
}

__device__ __host__ __forceinline__ int qpos(int K) {
    int ks = K >> 3, r = K & 7;
    int s = ((r & 3) << 1) | (r >> 2);
    return (ks >> 1) * 16 + (s >> 1) * 4 + (ks & 1) * 2 + (s & 1);
}

__global__ void prep_q(const float* __restrict__ qk, const float* __restrict__ qe) {
    int i = blockIdx.x * blockDim.x + threadIdx.x;      // over BSZ*4*MTOT
    if (i >= BSZ * HEADS_N * MTOT) return;
    int m = i & (MTOT - 1);
    int h = (i >> 10) & 3;
    int b = i >> 12;
    size_t qb = (size_t)i * 32;
    float bias = 0.0f;
    #pragma unroll
    for (int c = 0; c < 16; c++) {
        size_t gi = ((size_t)(b * 64 + h * 16 + c)) * MTOT + m;
        float e = qe[gi];
        float k = qk[gi];
        g_Q[qb + qpos(c)]      = rn_tf32(-e);
        g_Q[qb + qpos(16 + c)] = rn_tf32(2.0f * k * e);
        bias += e * k * k * k;
    }
    g_bias[i] = bias;
}

// mv -> fp16 fragment-native for m16n8k16. Thread f = b<<19|B16<<14|ngrp<<5|g<<2|t
// produces lane (g*4+t)'s 8 halves (16 bytes) for block (b,B16,ngrp).
// k-meaning within a 16-n group: k = 2*(n&7) + (n>>3)  (inverse: k=2t->n=t, 2t+1->t+8,
// 2t+8->t+4, 2t+9->t+12).
__global__ void prep_mv(const float* __restrict__ mv) {
    int f = blockIdx.x * blockDim.x + threadIdx.x;
    if (f >= BSZ * CVTOT * NTOT / 8) return;          // 1048576
    int t    = f & 3;
    int g    = (f >> 2) & 7;
    int ngrp = (f >> 5) & 511;
    int B16  = (f >> 14) & 31;
    int b    = f >> 19;
    const float* r0 = mv + (((size_t)(b * CVTOT + B16 * 16 + g)) << 13) + ngrp * 16;
    const float* r1 = r0 + ((size_t)8 << 13);
    __half2 x = __floats2half2_rn(r0[t],     r0[t + 8]);
    __half2 y = __floats2half2_rn(r1[t],     r1[t + 8]);
    __half2 z = __floats2half2_rn(r0[t + 4], r0[t + 12]);
    __half2 w = __floats2half2_rn(r1[t + 4], r1[t + 12]);
    uint4 v = { *(uint32_t*)&x, *(uint32_t*)&y, *(uint32_t*)&z, *(uint32_t*)&w };
    *(uint4*)((char*)g_mvph + (size_t)f * 16) = v;
}

// ---------------- main fused kernel ----------------
__global__ void __launch_bounds__(NTHREADS, 2)
mr_main(const float* __restrict__ ms)
{
    extern __shared__ float sm[];
    __half* smP = (__half*)(sm + F_P);
    const int tid  = threadIdx.x;
    const int w    = tid >> 5;       // 0..7
    const int lane = tid & 31;
    const int gid  = lane >> 2;      // 0..7
    const int tig  = lane & 3;       // 0..3

    const int bx    = blockIdx.x;    // 512 blocks
    const int split = bx & 7;
    const int mtile = (bx >> 3) & 31;
    const int b     = bx >> 8;
    const int m0    = mtile * M_T;
    const int nbase = split * NPS;

    // ---- stage bias + ms (whole split) + Q (block-constant) ----
    if (tid < 128)
        sm[F_BIAS + tid] = g_bias[(size_t)(b * HEADS_N + (tid >> 5)) * MTOT + m0 + (tid & 31)];
    #pragma unroll
    for (int it = 0; it < NPS / NTHREADS; it++) {
        int i = tid + it * NTHREADS;
        sm[F_MS + i] = ms[(size_t)b * NTOT + nbase + i];
    }
    {
        const float4* src = (const float4*)(g_Q + (size_t)(b * HEADS_N) * MTOT * 32);
        #pragma unroll
        for (int it = 0; it < 4; it++) {
            int j = tid + it * NTHREADS;         // 1024 float4
            int kq = j & 7, mm = (j >> 3) & 31, h = j >> 8;
            float4 v = src[((size_t)h * MTOT + m0 + mm) * 8 + kq];
            *(float4*)(sm + F_Q + (h * 32 + mm) * 48 + kq * 4) = v;
        }
    }

    // Phase A mapping: warp = (ntile 0..3, mtile2 0..1), all 4 heads in-register
    const int nt  = w & 3;
    const int mA0 = (w >> 2) * 16;
    // Phase B mapping: one head per 2 warps, 64cv x 32m per warp
    const int headB = w >> 1;
    const int cvq   = w & 1;

    float acc[4][4][4];   // O accumulators [cvblk16][mt][reg]
    #pragma unroll
    for (int rt = 0; rt < 4; rt++)
        #pragma unroll
        for (int mt = 0; mt < 4; mt++)
            #pragma unroll
            for (int r = 0; r < 4; r++) acc[rt][mt][r] = 0.0f;

    // fragment-native bases
    const __half* gmb0 = g_mvph +
        ((size_t)(b * 32 + headB * 8 + cvq * 4) * 512) * 256 + lane * 8;
    const float* ktb0 = g_ktf + ((size_t)(b * HEADS_N) * (NTOT / 16)) * 512;
    const __half* pbh = smP + headB * (32 * PSTRH);
    const int prd = ((gid >> 2) & 1) * 16;   // reader swizzle

    const float SC = 0.18033688f;   // 0.125 * log2(e)

    __syncthreads();

    for (int chunk = 0; chunk < NCHUNKS; chunk++) {
        const int n0 = nbase + chunk * NCH;

        // ===== Phase A (tf32): two 64-n sub-passes =====
        #pragma unroll
        for (int p = 0; p < 2; p++) {
            float sacc[4][2][4];
            #pragma unroll
            for (int h = 0; h < 4; h++)
                #pragma unroll
                for (int j = 0; j < 2; j++)
                    #pragma unroll
                    for (int r = 0; r < 4; r++) sacc[h][j][r] = 0.0f;

            const int ngrp = (n0 >> 4) + p * 4 + nt;
            #pragma unroll
            for (int kp = 0; kp < 2; kp++) {
                #pragma unroll
                for (int h = 0; h < 4; h++) {
                    const float* kb = ktb0 +
                        (((size_t)h * (NTOT / 16) + ngrp) * 4 + 2 * kp) * 128 + lane * 4;
                    float4 fA0 = *(const float4*)(kb);
                    float4 fA1 = *(const float4*)(kb + 128);
                    const float* qb = sm + F_Q + h * 1536 + kp * 16 + tig * 4;
                    #pragma unroll
                    for (int j = 0; j < 2; j++) {
                        float4 bq = *(const float4*)(qb + (mA0 + j * 8 + gid) * 48);
                        mma_tf32(sacc[h][j], make_float2(fA0.x, fA0.y),
                                 make_float2(fA0.z, fA0.w), make_float2(bq.x, bq.y));
                        mma_tf32(sacc[h][j], make_float2(fA1.x, fA1.y),
                                 make_float2(fA1.z, fA1.w), make_float2(bq.z, bq.w));
                    }
                }
            }

            // ---- softmax over heads (log2 domain), pack fp16 pairs, store P ----
            {
                const int nAl = p * 64 + nt * 16 + gid;
                const float msa = sm[F_MS + chunk * NCH + nAl] * SC;
                const float msb = sm[F_MS + chunk * NCH + nAl + 8] * SC;
                const int grp = p * 4 + nt;
                const int woff = grp * 16 + (gid & 3) * 4 + (gid >> 2) * 2;
                #pragma unroll
                for (int j = 0; j < 2; j++) {
                    #pragma unroll
                    for (int c = 0; c < 2; c++) {
                        int m = mA0 + j * 8 + 2 * tig + c;
                        float b0 = sm[F_BIAS + m];
                        float b1 = sm[F_BIAS + 32 + m];
                        float b2 = sm[F_BIAS + 64 + m];
                        float b3 = sm[F_BIAS + 96 + m];
                        float ea0 = ex2f((sacc[0][j][c] - b0) * msa);
                        float ea1 = ex2f((sacc[1][j][c] - b1) * msa);
                        float ea2 = ex2f((sacc[2][j][c] - b2) * msa);
                        float ea3 = ex2f((sacc[3][j][c] - b3) * msa);
                        float inva = __fdividef(1.0f, ea0 + ea1 + ea2 + ea3 + 1e-30f);
                        float eb0 = ex2f((sacc[0][j][2 + c] - b0) * msb);
                        float eb1 = ex2f((sacc[1][j][2 + c] - b1) * msb);
                        float eb2 = ex2f((sacc[2][j][2 + c] - b2) * msb);
                        float eb3 = ex2f((sacc[3][j][2 + c] - b3) * msb);
                        float invb = __fdividef(1.0f, eb0 + eb1 + eb2 + eb3 + 1e-30f);
                        uint32_t pk0 = pack_h2(ea0 * inva, eb0 * invb);
                        uint32_t pk1 = pack_h2(ea1 * inva, eb1 * invb);
                        uint32_t pk2v = pack_h2(ea2 * inva, eb2 * invb);
                        uint32_t pk3 = pack_h2(ea3 * inva, eb3 * invb);
                        int roff = m * PSTRH + woff + ((m >> 2) & 1) * 16;
                        *(uint32_t*)(smP + roff)              = pk0;
                        *(uint32_t*)(smP + 32 * PSTRH + roff) = pk1;
                        *(uint32_t*)(smP + 64 * PSTRH + roff) = pk2v;
                        *(uint32_t*)(smP + 96 * PSTRH + roff) = pk3;
                    }
                }
            }
        }
        __syncthreads();

        // ===== Phase B (fp16 m16n8k16): O += mv * P over 128 n =====
        #pragma unroll
        for (int g16 = 0; g16 < 8; g16++) {
            const size_t ngrp = (size_t)(n0 >> 4) + g16;
            uint4 av0 = *(const uint4*)(gmb0 + (0 * 512 + ngrp) * 256);
            uint4 av1 = *(const uint4*)(gmb0 + (1 * 512 + ngrp) * 256);
            uint4 av2 = *(const uint4*)(gmb0 + (2 * 512 + ngrp) * 256);
            uint4 av3 = *(const uint4*)(gmb0 + (3 * 512 + ngrp) * 256);
            #pragma unroll
            for (int mt = 0; mt < 4; mt++) {
                uint2 bb = *(const uint2*)(pbh + (mt * 8 + gid) * PSTRH + g16 * 16
                                           + tig * 4 + prd);
                mma_f16(acc[0][mt], av0, bb);
                mma_f16(acc[1][mt], av1, bb);
                mma_f16(acc[2][mt], av2, bb);
                mma_f16(acc[3][mt], av3, bb);
            }
        }
        __syncthreads();
    }

    // ---- writeout: fragment-direct STG.64 into g_partial ----
    {
        const int cv0 = headB * 128 + cvq * 64;
        float* pp = g_partial +
            ((size_t)(split * BSZ + b) * CVTOT + cv0) * MTOT + m0;
        #pragma unroll
        for (int blk = 0; blk < 4; blk++) {
            #pragma unroll
            for (int mt = 0; mt < 4; mt++) {
                int m = mt * 8 + 2 * tig;
                float2 lo = { acc[blk][mt][0], acc[blk][mt][1] };
                float2 hi = { acc[blk][mt][2], acc[blk][mt][3] };
                *(float2*)(pp + (size_t)(blk * 16 + gid) * MTOT + m)     = lo;
                *(float2*)(pp + (size_t)(blk * 16 + gid + 8) * MTOT + m) = hi;
            }
        }
    }
}

// ---------------- assemble: reduce 8 splits + copy qv ----------------
__global__ void assemble_kernel(const float* __restrict__ qv, float* __restrict__ out)
{
    const int total4 = BSZ * 2 * CVTOT * MTOT / 4;
    int idx = blockIdx.x * blockDim.x + threadIdx.x;
    if (idx >= total4) return;
    int gf  = idx * 4;
    int b   = gf >> 20;
    int rem = gf & ((1 << 20) - 1);
    int ch  = rem >> 10;
    int m   = rem & 1023;

    float4 r;
    if (ch < CVTOT) {
        const size_t stride = (size_t)BSZ * CVTOT * MTOT;
        size_t off = ((size_t)b * CVTOT + ch) * MTOT + m;
        r = make_float4(0.f, 0.f, 0.f, 0.f);
        #pragma unroll
        for (int s = 0; s < NSPLIT; s++) {
            float4 a = *reinterpret_cast<const float4*>(g_partial + s * stride + off);
            r.x += a.x; r.y += a.y; r.z += a.z; r.w += a.w;
        }
    } else {
        r = *reinterpret_cast<const float4*>(
                qv + ((size_t)b * CVTOT + (ch - CVTOT)) * MTOT + m);
    }
    *reinterpret_cast<float4*>(out + (size_t)gf) = r;
}

extern "C" void kernel_launch(void* const* d_in, const int* in_sizes, int n_in,
                              void* d_out, int out_size)
{
    const float* mk = (const float*)d_in[0];
    const float* qk = (const float*)d_in[1];
    const float* ms = (const float*)d_in[2];
    const float* qe = (const float*)d_in[3];
    const float* mv = (const float*)d_in[4];
    const float* qv = (const float*)d_in[5];
    float* out = (float*)d_out;

    prep_ktf<<<(BSZ * 64 * NTOT + 255) / 256, 256>>>(mk);
    prep_q<<<(BSZ * HEADS_N * MTOT + 255) / 256, 256>>>(qk, qe);
    prep_mv<<<(BSZ * CVTOT * NTOT / 8 + 255) / 256, 256>>>(mv);

    cudaFuncSetAttribute(mr_main, cudaFuncAttributeMaxDynamicSharedMemorySize,
                         SM_TOTAL);
    mr_main<<<BSZ * (MTOT / M_T) * NSPLIT, NTHREADS, SM_TOTAL>>>(ms);

    const int total4 = BSZ * 2 * CVTOT * MTOT / 4;
    assemble_kernel<<<(total4 + 255) / 256, 256>>>(qv, out);
}

// round 15
// speedup vs baseline: 1.9404x; 1.1923x over previous
#include <cuda_runtime.h>
#include <cuda_fp16.h>
#include <cstdint>

// ---------------- problem constants ----------------
#define HEADS_N 4
#define BSZ 2
#define NTOT 8192        // THW
#define MTOT 1024        // HW
#define CVTOT 512
#define M_T 32           // m-tile per block
#define NSPLIT 8
#define NPS (NTOT / NSPLIT)     // 1024
#define NCH 128                 // n per chunk
#define NCHUNKS (NPS / NCH)     // 8
#define NTHREADS 256
#define PSTRH 144               // P row stride in halves (72 words == 8 mod 32)
#define QSTR 80                 // Q row stride in halves (40 words == 8 mod 32)
#define PBUF (4 * 32 * PSTRH)   // 18432 halves per P buffer

// ---------------- device scratch (no cudaMalloc allowed) ----------------
__device__ __align__(16) float g_partial[NSPLIT * BSZ * CVTOT * MTOT]; // 32 MB
// Kt fp16 fragment-native (m16n8k16 A): [b][h][ngrp(512)][kstep(2)][lane(32)][8]  (4 MB)
__device__ __align__(16) __half g_kth[BSZ * HEADS_N * 512 * 2 * 256];
// Q fp16: [b][h][m][32 halves, fragment-ordered]  (0.5 MB)
__device__ __align__(16) __half g_Qh[BSZ * HEADS_N * MTOT * 32];
__device__ __align__(16) float g_bias[BSZ * HEADS_N * MTOT];           // 32 KB
// mv fp16 fragment-native for m16n8k16: [b][B16(32)][ngrp(512)][lane(32)][8] (16.7 MB)
__device__ __align__(16) __half g_mvph[BSZ * CVTOT * NTOT];

// ---------------- smem layout (float offsets) ----------------
#define F_BIAS 0                          // bias[4][32] fp32
#define F_MS   128                        // ms[1024] fp32
#define F_QH   (F_MS + NPS)               // 1152 : Q fp16 [4][32][QSTR]
#define F_PH   (F_QH + 4 * 32 * QSTR / 2) // 3712 : P fp16, 2 buffers of PBUF halves
#define SM_TOTAL ((F_PH + 2 * PBUF / 2) * 4)   // 51712 B

// ---------------- helpers ----------------
__device__ __forceinline__ float ex2f(float x) {
    float y;
    asm("ex2.approx.f32 %0, %1;" : "=f"(y) : "f"(x));
    return y;
}
// pack (lo, hi) floats into fp16x2 (lo -> low half)
__device__ __forceinline__ uint32_t pack_h2(float lo, float hi) {
    uint32_t r;
    asm("cvt.rn.f16x2.f32 %0, %1, %2;" : "=r"(r) : "f"(hi), "f"(lo));
    return r;
}
__device__ __forceinline__ void mma_f16(float* d, uint4 a, uint2 b) {
    asm volatile(
        "mma.sync.aligned.m16n8k16.row.col.f32.f16.f16.f32 "
        "{%0,%1,%2,%3},{%4,%5,%6,%7},{%8,%9},{%0,%1,%2,%3};"
        : "+f"(d[0]), "+f"(d[1]), "+f"(d[2]), "+f"(d[3])
        : "r"(a.x), "r"(a.y), "r"(a.z), "r"(a.w), "r"(b.x), "r"(b.y));
}

// ---------------- precompute kernels ----------------
// Kt fp16 fragment-native: logical K<16 -> mk^3 (kstep0), K>=16 -> mk (kstep1)
__global__ void prep_kth(const float* __restrict__ mk) {
    int i = blockIdx.x * blockDim.x + threadIdx.x;      // over BSZ*64*NTOT
    if (i >= BSZ * 64 * NTOT) return;
    int n  = i & (NTOT - 1);
    int ck = (i >> 13) & 63;
    int b  = i >> 19;
    float v = mk[i];
    int h = ck >> 4, c = ck & 15;
    int ngrp = n >> 4, nn = n & 15, g = nn & 7, hf = nn >> 3;
    int t = (c & 7) >> 1, d = c & 1, s = c >> 3;
    int hp = s * 4 + hf * 2 + d;
    size_t base = ((((size_t)(b * HEADS_N + h) * 512 + ngrp) * 2) * 32
                   + (g * 4 + t)) * 8 + hp;
    g_kth[base]       = __float2half_rn(v * v * v);   // kstep 0
    g_kth[base + 256] = __float2half_rn(v);           // kstep 1
}

// fragment position of kk (0..15) within a 16-k step: 4t + 2s + d
__device__ __forceinline__ int pos16(int kk) {
    return 4 * ((kk & 7) >> 1) + 2 * (kk >> 3) + (kk & 1);
}

__global__ void prep_q(const float* __restrict__ qk, const float* __restrict__ qe) {
    int i = blockIdx.x * blockDim.x + threadIdx.x;      // over BSZ*4*MTOT
    if (i >= BSZ * HEADS_N * MTOT) return;
    int m = i & (MTOT - 1);
    int h = (i >> 10) & 3;
    int b = i >> 12;
    size_t qb = (size_t)i * 32;
    float bias = 0.0f;
    #pragma unroll
    for (int c = 0; c < 16; c++) {
        size_t gi = ((size_t)(b * 64 + h * 16 + c)) * MTOT + m;
        float e = qe[gi];
        float k = qk[gi];
        int p = pos16(c);
        g_Qh[qb + p]      = __float2half_rn(-e);           // K=c (kstep 0)
        g_Qh[qb + 16 + p] = __float2half_rn(2.0f * k * e); // K=c+16 (kstep 1)
        bias += e * k * k * k;
    }
    g_bias[i] = bias;
}

// mv -> fp16 fragment-native (unchanged from R14)
__global__ void prep_mv(const float* __restrict__ mv) {
    int f = blockIdx.x * blockDim.x + threadIdx.x;
    if (f >= BSZ * CVTOT * NTOT / 8) return;
    int t    = f & 3;
    int g    = (f >> 2) & 7;
    int ngrp = (f >> 5) & 511;
    int B16  = (f >> 14) & 31;
    int b    = f >> 19;
    const float* r0 = mv + (((size_t)(b * CVTOT + B16 * 16 + g)) << 13) + ngrp * 16;
    const float* r1 = r0 + ((size_t)8 << 13);
    __half2 x = __floats2half2_rn(r0[t],     r0[t + 8]);
    __half2 y = __floats2half2_rn(r1[t],     r1[t + 8]);
    __half2 z = __floats2half2_rn(r0[t + 4], r0[t + 12]);
    __half2 w = __floats2half2_rn(r1[t + 4], r1[t + 12]);
    uint4 v = { *(uint32_t*)&x, *(uint32_t*)&y, *(uint32_t*)&z, *(uint32_t*)&w };
    *(uint4*)((char*)g_mvph + (size_t)f * 16) = v;
}

// ---------------- main fused kernel ----------------
__global__ void __launch_bounds__(NTHREADS, 2)
mr_main(const float* __restrict__ ms)
{
    extern __shared__ float sm[];
    __half* smQ = (__half*)(sm + F_QH);
    __half* smP = (__half*)(sm + F_PH);
    const int tid  = threadIdx.x;
    const int w    = tid >> 5;       // 0..7
    const int lane = tid & 31;
    const int gid  = lane >> 2;      // 0..7
    const int tig  = lane & 3;       // 0..3

    const int bx    = blockIdx.x;    // 512 blocks
    const int split = bx & 7;
    const int mtile = (bx >> 3) & 31;
    const int b     = bx >> 8;
    const int m0    = mtile * M_T;
    const int nbase = split * NPS;

    // ---- stage bias + ms (whole split) + Q fp16 (block-constant) ----
    if (tid < 128)
        sm[F_BIAS + tid] = g_bias[(size_t)(b * HEADS_N + (tid >> 5)) * MTOT + m0 + (tid & 31)];
    #pragma unroll
    for (int it = 0; it < NPS / NTHREADS; it++) {
        int i = tid + it * NTHREADS;
        sm[F_MS + i] = ms[(size_t)b * NTOT + nbase + i];
    }
    {
        const uint4* qsrc = (const uint4*)(g_Qh + ((size_t)(b * HEADS_N) * MTOT) * 32);
        #pragma unroll
        for (int it = 0; it < 2; it++) {
            int j = tid + it * NTHREADS;         // 512 uint4
            int q = j & 3, mm = (j >> 2) & 31, h = j >> 7;
            uint4 v = qsrc[((size_t)h * MTOT + m0 + mm) * 4 + q];
            *(uint4*)(smQ + (h * 32 + mm) * QSTR + ((mm >> 2) & 1) * 16 + q * 8) = v;
        }
    }

    // Phase A mapping: warp = (ntile 0..3, mtile2 0..1), all 4 heads in-register
    const int nt  = w & 3;
    const int mA0 = (w >> 2) * 16;
    // Phase B mapping: one head per 2 warps, 64cv x 32m per warp
    const int headB = w >> 1;
    const int cvq   = w & 1;

    float acc[4][4][4];   // O accumulators [cvblk16][mt][reg]
    #pragma unroll
    for (int rt = 0; rt < 4; rt++)
        #pragma unroll
        for (int mt = 0; mt < 4; mt++)
            #pragma unroll
            for (int r = 0; r < 4; r++) acc[rt][mt][r] = 0.0f;

    // fragment-native bases
    const __half* gmb0 = g_mvph +
        ((size_t)(b * 32 + headB * 8 + cvq * 4) * 512) * 256 + lane * 8;
    const __half* kthb = g_kth + (size_t)(b * HEADS_N) * 512 * 2 * 256;
    const __half* pbh0 = smP + headB * (32 * PSTRH);
    const int prd = ((gid >> 2) & 1) * 16;   // reader shift (matches writer)
    const int qsh = ((gid >> 2) & 1) * 16;   // Q reader shift

    const float SC = 0.18033688f;   // 0.125 * log2(e)

    __syncthreads();

    for (int chunk = 0; chunk < NCHUNKS; chunk++) {
        const int n0 = nbase + chunk * NCH;
        const int pbuf = (chunk & 1) * PBUF;

        // ===== Phase A (fp16 m16n8k16): two 64-n sub-passes =====
        #pragma unroll
        for (int p = 0; p < 2; p++) {
            float sacc[4][2][4];
            #pragma unroll
            for (int h = 0; h < 4; h++)
                #pragma unroll
                for (int j = 0; j < 2; j++)
                    #pragma unroll
                    for (int r = 0; r < 4; r++) sacc[h][j][r] = 0.0f;

            const int ngrp = (n0 >> 4) + p * 4 + nt;
            #pragma unroll
            for (int ks = 0; ks < 2; ks++) {
                #pragma unroll
                for (int h = 0; h < 4; h++) {
                    uint4 aA = *(const uint4*)(kthb +
                        (((size_t)h * 512 + ngrp) * 2 + ks) * 256 + lane * 8);
                    #pragma unroll
                    for (int j = 0; j < 2; j++) {
                        uint2 bq = *(const uint2*)(smQ +
                            (h * 32 + mA0 + j * 8 + gid) * QSTR + ks * 16 + tig * 4 + qsh);
                        mma_f16(sacc[h][j], aA, bq);
                    }
                }
            }

            // ---- softmax over heads (log2 domain), pack fp16 pairs, store P ----
            {
                const int nAl = p * 64 + nt * 16 + gid;
                const float msa = sm[F_MS + chunk * NCH + nAl] * SC;
                const float msb = sm[F_MS + chunk * NCH + nAl + 8] * SC;
                const int grp = p * 4 + nt;
                const int woff = grp * 16 + (gid & 3) * 4 + (gid >> 2) * 2;
                #pragma unroll
                for (int j = 0; j < 2; j++) {
                    #pragma unroll
                    for (int c = 0; c < 2; c++) {
                        int m = mA0 + j * 8 + 2 * tig + c;
                        float b0 = sm[F_BIAS + m];
                        float b1 = sm[F_BIAS + 32 + m];
                        float b2 = sm[F_BIAS + 64 + m];
                        float b3 = sm[F_BIAS + 96 + m];
                        float ea0 = ex2f((sacc[0][j][c] - b0) * msa);
                        float ea1 = ex2f((sacc[1][j][c] - b1) * msa);
                        float ea2 = ex2f((sacc[2][j][c] - b2) * msa);
                        float ea3 = ex2f((sacc[3][j][c] - b3) * msa);
                        float inva = __fdividef(1.0f, ea0 + ea1 + ea2 + ea3 + 1e-30f);
                        float eb0 = ex2f((sacc[0][j][2 + c] - b0) * msb);
                        float eb1 = ex2f((sacc[1][j][2 + c] - b1) * msb);
                        float eb2 = ex2f((sacc[2][j][2 + c] - b2) * msb);
                        float eb3 = ex2f((sacc[3][j][2 + c] - b3) * msb);
                        float invb = __fdividef(1.0f, eb0 + eb1 + eb2 + eb3 + 1e-30f);
                        uint32_t pk0  = pack_h2(ea0 * inva, eb0 * invb);
                        uint32_t pk1  = pack_h2(ea1 * inva, eb1 * invb);
                        uint32_t pk2v = pack_h2(ea2 * inva, eb2 * invb);
                        uint32_t pk3  = pack_h2(ea3 * inva, eb3 * invb);
                        int roff = pbuf + m * PSTRH + woff + ((m >> 2) & 1) * 16;
                        *(uint32_t*)(smP + roff)              = pk0;
                        *(uint32_t*)(smP + 32 * PSTRH + roff) = pk1;
                        *(uint32_t*)(smP + 64 * PSTRH + roff) = pk2v;
                        *(uint32_t*)(smP + 96 * PSTRH + roff) = pk3;
                    }
                }
            }
        }
        __syncthreads();   // single sync per chunk (double-buffered P)

        // ===== Phase B (fp16 m16n8k16): O += mv * P over 128 n =====
        const __half* pbh = pbh0 + pbuf;
        #pragma unroll
        for (int g16 = 0; g16 < 8; g16++) {
            const size_t ngrp = (size_t)(n0 >> 4) + g16;
            uint4 av0 = *(const uint4*)(gmb0 + (0 * 512 + ngrp) * 256);
            uint4 av1 = *(const uint4*)(gmb0 + (1 * 512 + ngrp) * 256);
            uint4 av2 = *(const uint4*)(gmb0 + (2 * 512 + ngrp) * 256);
            uint4 av3 = *(const uint4*)(gmb0 + (3 * 512 + ngrp) * 256);
            #pragma unroll
            for (int mt = 0; mt < 4; mt++) {
                uint2 bb = *(const uint2*)(pbh + (mt * 8 + gid) * PSTRH + g16 * 16
                                           + tig * 4 + prd);
                mma_f16(acc[0][mt], av0, bb);
                mma_f16(acc[1][mt], av1, bb);
                mma_f16(acc[2][mt], av2, bb);
                mma_f16(acc[3][mt], av3, bb);
            }
        }
    }

    // ---- writeout: fragment-direct STG.64 into g_partial ----
    {
        const int cv0 = headB * 128 + cvq * 64;
        float* pp = g_partial +
            ((size_t)(split * BSZ + b) * CVTOT + cv0) * MTOT + m0;
        #pragma unroll
        for (int blk = 0; blk < 4; blk++) {
            #pragma unroll
            for (int mt = 0; mt < 4; mt++) {
                int m = mt * 8 + 2 * tig;
                float2 lo = { acc[blk][mt][0], acc[blk][mt][1] };
                float2 hi = { acc[blk][mt][2], acc[blk][mt][3] };
                *(float2*)(pp + (size_t)(blk * 16 + gid) * MTOT + m)     = lo;
                *(float2*)(pp + (size_t)(blk * 16 + gid + 8) * MTOT + m) = hi;
            }
        }
    }
}

// ---------------- assemble: reduce 8 splits + copy qv ----------------
__global__ void assemble_kernel(const float* __restrict__ qv, float* __restrict__ out)
{
    const int total4 = BSZ * 2 * CVTOT * MTOT / 4;
    int idx = blockIdx.x * blockDim.x + threadIdx.x;
    if (idx >= total4) return;
    int gf  = idx * 4;
    int b   = gf >> 20;
    int rem = gf & ((1 << 20) - 1);
    int ch  = rem >> 10;
    int m   = rem & 1023;

    float4 r;
    if (ch < CVTOT) {
        const size_t stride = (size_t)BSZ * CVTOT * MTOT;
        size_t off = ((size_t)b * CVTOT + ch) * MTOT + m;
        r = make_float4(0.f, 0.f, 0.f, 0.f);
        #pragma unroll
        for (int s = 0; s < NSPLIT; s++) {
            float4 a = *reinterpret_cast<const float4*>(g_partial + s * stride + off);
            r.x += a.x; r.y += a.y; r.z += a.z; r.w += a.w;
        }
    } else {
        r = *reinterpret_cast<const float4*>(
                qv + ((size_t)b * CVTOT + (ch - CVTOT)) * MTOT + m);
    }
    *reinterpret_cast<float4*>(out + (size_t)gf) = r;
}

extern "C" void kernel_launch(void* const* d_in, const int* in_sizes, int n_in,
                              void* d_out, int out_size)
{
    const float* mk = (const float*)d_in[0];
    const float* qk = (const float*)d_in[1];
    const float* ms = (const float*)d_in[2];
    const float* qe = (const float*)d_in[3];
    const float* mv = (const float*)d_in[4];
    const float* qv = (const float*)d_in[5];
    float* out = (float*)d_out;

    prep_kth<<<(BSZ * 64 * NTOT + 255) / 256, 256>>>(mk);
    prep_q<<<(BSZ * HEADS_N * MTOT + 255) / 256, 256>>>(qk, qe);
    prep_mv<<<(BSZ * CVTOT * NTOT / 8 + 255) / 256, 256>>>(mv);

    cudaFuncSetAttribute(mr_main, cudaFuncAttributeMaxDynamicSharedMemorySize,
                         SM_TOTAL);
    mr_main<<<BSZ * (MTOT / M_T) * NSPLIT, NTHREADS, SM_TOTAL>>>(ms);

    const int total4 = BSZ * 2 * CVTOT * MTOT / 4;
    assemble_kernel<<<(total4 + 255) / 256, 256>>>(qv, out);
}